// round 12
// baseline (speedup 1.0000x reference)
#include <cuda_runtime.h>
#include <cuda_fp16.h>
#include <cstdint>

// GRU cell B=8192, I=H=1024 fp32. mma.sync fp16 m16n8k16 (fp32 accum).
// R12: GEMMs = R9 verbatim (best). perm rewritten: smem-staged transpose so
// BOTH global loads and global stores are fully coalesced; 1D grid, no empty
// blocks. Output layout/values bit-identical to R4 perm.

#define BB 8192
#define HH 1024
#define KK 1024

// Fragment layouts (validated R4):
//  A: g_ap[((rb*64+kb)*32+lane)] = uint4{a0,a1,a2,a3}, lane=g*4+tq
//  B: g_Wh[w][((nb*64+kb)*32+lane)] = uint2{b0,b1}
__device__ __align__(16) uint4 g_xp[BB * KK / 8];
__device__ __align__(16) uint4 g_hp[BB * KK / 8];
__device__ __align__(16) uint4 g_rhp[BB * KK / 8];
__device__ __align__(16) float g_Z[BB * HH];
__device__ __align__(16) uint2 g_Wh[6][HH * KK / 4];  // 0:Wwz 1:Wuz 2:Wwr 3:Wur 4:Wu 5:Ww

__device__ __forceinline__ void cp_async16(void* sdst, const void* gsrc) {
    uint32_t s = (uint32_t)__cvta_generic_to_shared(sdst);
    asm volatile("cp.async.cg.shared.global [%0], [%1], 16;\n" :: "r"(s), "l"(gsrc));
}
__device__ __forceinline__ void cp_commit() { asm volatile("cp.async.commit_group;\n"); }
__device__ __forceinline__ void cp_wait1() { asm volatile("cp.async.wait_group 1;\n"); }
__device__ __forceinline__ void cp_wait0() { asm volatile("cp.async.wait_group 0;\n"); }

__device__ __forceinline__ void mma16(float c[4], const uint4& a, const uint2& b) {
    asm volatile(
        "mma.sync.aligned.m16n8k16.row.col.f32.f16.f16.f32 "
        "{%0,%1,%2,%3},{%4,%5,%6,%7},{%8,%9},{%0,%1,%2,%3};\n"
        : "+f"(c[0]), "+f"(c[1]), "+f"(c[2]), "+f"(c[3])
        : "r"(a.x), "r"(a.y), "r"(a.z), "r"(a.w), "r"(b.x), "r"(b.y));
}
__device__ __forceinline__ float sig_(float v) { return 1.0f / (1.0f + __expf(-v)); }
__device__ __forceinline__ float ftanh_(float v) {
    return 1.0f - 2.0f / (1.0f + __expf(2.0f * v));
}
__device__ __forceinline__ uint32_t h2u(float a, float b) {
    __half2 h = __floats2half2_rn(a, b);
    return *reinterpret_cast<uint32_t*>(&h);
}

// ---------------------------------------------------------------------------
// Preprocess (R12): smem-transposed, coalesced loads AND stores, 1D grid.
//  blocks [0, 8192): A tensors. b>>12: 0=x 1=h; rb=(b>>3)&511; kbc=b&7.
//    tile = 16 rows x 128 cols fp32 -> 256 fragment uint4 (4KB contiguous).
//  blocks [8192, 14336): weights. widx=(b-8192)>>10; nb, kbc from low bits.
//    tile = 8 rows x 128 cols fp32 -> 256 fragment uint2 (2KB contiguous).
// ---------------------------------------------------------------------------
__global__ void __launch_bounds__(256) perm_all(
    const float* __restrict__ x, const float* __restrict__ hm,
    const float* __restrict__ w0, const float* __restrict__ w1,
    const float* __restrict__ w2, const float* __restrict__ w3,
    const float* __restrict__ w4, const float* __restrict__ w5) {
    __shared__ uint32_t sm[8 * 33 * 4];   // padded fragment image
    const int b = blockIdx.x;
    const int t = threadIdx.x;

    if (b < 8192) {
        const float* src = (b & 4096) ? hm : x;
        uint4* dst = (b & 4096) ? g_hp : g_xp;
        const int rb = (b >> 3) & 511, kbc = b & 7;
        const float4* s = reinterpret_cast<const float4*>(src + (rb * 16) * KK + kbc * 128);
        #pragma unroll
        for (int i = 0; i < 2; i++) {
            int f = t + i * 256;              // 512 float4 = 16 rows x 32
            int row = f >> 5, c4 = f & 31;
            float4 v = s[row * 256 + c4];     // row stride = KK/4
            uint32_t p0 = h2u(v.x, v.y);      // pair at col 4c4
            uint32_t p1 = h2u(v.z, v.w);      // pair at col 4c4+2
            int g_ = row & 7, cr = row >> 3;
            int cp0 = c4 * 2;
            int kb0 = cp0 >> 3, j0 = cp0 & 7;
            sm[((kb0 * 33) + g_ * 4 + (j0 & 3)) * 4 + cr + 2 * (j0 >> 2)] = p0;
            int cp1 = cp0 + 1;
            int kb1 = cp1 >> 3, j1 = cp1 & 7;
            sm[((kb1 * 33) + g_ * 4 + (j1 & 3)) * 4 + cr + 2 * (j1 >> 2)] = p1;
        }
        __syncthreads();
        {
            int kb = t >> 5, lane = t & 31;
            dst[(rb * 64 + kbc * 8 + kb) * 32 + lane] =
                reinterpret_cast<const uint4*>(sm)[kb * 33 + lane];
        }
    } else {
        const int wb = b - 8192;
        const int widx = wb >> 10;
        const int bb = wb & 1023;
        const int nb = bb >> 3, kbc = bb & 7;
        const float* srcs[6] = {w0, w1, w2, w3, w4, w5};
        const float4* s = reinterpret_cast<const float4*>(srcs[widx] + (nb * 8) * KK + kbc * 128);
        {
            int f = t;                        // 256 float4 = 8 rows x 32
            int row = f >> 5, c4 = f & 31;
            float4 v = s[row * 256 + c4];
            uint32_t p0 = h2u(v.x, v.y);
            uint32_t p1 = h2u(v.z, v.w);
            int cp0 = c4 * 2;
            int kb0 = cp0 >> 3, j0 = cp0 & 7;
            sm[(kb0 * 33 + row * 4 + (j0 & 3)) * 2 + (j0 >> 2)] = p0;
            int cp1 = cp0 + 1;
            int kb1 = cp1 >> 3, j1 = cp1 & 7;
            sm[(kb1 * 33 + row * 4 + (j1 & 3)) * 2 + (j1 >> 2)] = p1;
        }
        __syncthreads();
        {
            int kb = t >> 5, lane = t & 31;
            g_Wh[widx][(nb * 64 + kbc * 8 + kb) * 32 + lane] =
                reinterpret_cast<const uint2*>(sm)[kb * 33 + lane];
        }
    }
}

// ---------------------------------------------------------------------------
// Kernel 1 (R9 verbatim): dual-acc z/r GEMM. Block 128x64, 8 warps (4m x 2n),
// warp 32x32 dual, BK=64, 3-stage ring. smem/stage (uint4): A 1024 | Bz 512 |
// Br 512. 3 stages = 96KB, 2 CTAs/SM.
// ---------------------------------------------------------------------------
__global__ void __launch_bounds__(256, 2) gemm_zr(const float* __restrict__ h) {
    extern __shared__ uint4 sm4[];
    const int tid = threadIdx.x, wid = tid >> 5, lane = tid & 31;
    const int g = lane >> 2, tq = lane & 3;
    const int bm = blockIdx.x * 128, bn = blockIdx.y * 64;
    const int rb0 = bm >> 4, nb0 = bn >> 3;

    auto stage = [&](int t) {
        const int seg = t >> 4, kb = (t & 15) * 4;
        const uint4* Ag = seg ? g_hp : g_xp;
        const uint4* Bz = reinterpret_cast<const uint4*>(g_Wh[seg ? 1 : 0]);
        const uint4* Br = reinterpret_cast<const uint4*>(g_Wh[seg ? 3 : 2]);
        uint4* dst = &sm4[(t % 3) * 2048];
        #pragma unroll
        for (int i = 0; i < 4; i++) {
            int c = tid + i * 256, rbl = c >> 7, rem = c & 127;
            cp_async16(&dst[c], &Ag[((rb0 + rbl) * 64 + kb) * 32 + rem]);
        }
        #pragma unroll
        for (int i = 0; i < 2; i++) {
            int c = tid + i * 256, nbl = c >> 6, rem = c & 63;
            int so = ((nb0 + nbl) * 64 + kb) * 16 + rem;
            cp_async16(&dst[1024 + c], &Bz[so]);
            cp_async16(&dst[1536 + c], &Br[so]);
        }
        cp_commit();
    };

    float accZ[2][4][4] = {}, accR[2][4][4] = {};
    stage(0);
    stage(1);

    const int r0 = (wid & 3) * 2, nbl = (wid >> 2) * 4;
    for (int t = 0; t < 32; t++) {
        if (t + 2 < 32) cp_wait1(); else cp_wait0();
        __syncthreads();
        if (t + 2 < 32) stage(t + 2);
        const uint4* A_ = &sm4[(t % 3) * 2048];
        const uint2* Bz_ = reinterpret_cast<const uint2*>(&A_[1024]);
        const uint2* Br_ = reinterpret_cast<const uint2*>(&A_[1536]);
        #pragma unroll
        for (int kk = 0; kk < 4; kk++) {
            uint4 a0 = A_[(r0 * 4 + kk) * 32 + lane];
            uint4 a1 = A_[((r0 + 1) * 4 + kk) * 32 + lane];
            #pragma unroll
            for (int nt = 0; nt < 4; nt++) {
                uint2 bz = Bz_[(nbl + nt) * 128 + kk * 32 + lane];
                uint2 br = Br_[(nbl + nt) * 128 + kk * 32 + lane];
                mma16(accZ[0][nt], a0, bz);
                mma16(accZ[1][nt], a1, bz);
                mma16(accR[0][nt], a0, br);
                mma16(accR[1][nt], a1, br);
            }
        }
    }

    // epilogue: z f32; rh fp16 fragment-ordered (validated R4)
    uint32_t* rhp32 = reinterpret_cast<uint32_t*>(g_rhp);
    const int wm = (wid & 3) * 32, wn = (wid >> 2) * 32;
    #pragma unroll
    for (int mt = 0; mt < 2; mt++) {
        const int rbase = bm + wm + mt * 16;
        #pragma unroll
        for (int nt = 0; nt < 4; nt++) {
            const int colb = bn + wn + nt * 8 + tq * 2;
            const int kb = ((bn + wn) >> 4) + (nt >> 1);
            #pragma unroll
            for (int half = 0; half < 2; half++) {
                const int row = rbase + half * 8 + g;
                const int idx = row * HH + colb;
                float2 hv = *reinterpret_cast<const float2*>(&h[idx]);
                float2 zo;
                zo.x = sig_(accZ[mt][nt][half * 2]);
                zo.y = sig_(accZ[mt][nt][half * 2 + 1]);
                *reinterpret_cast<float2*>(&g_Z[idx]) = zo;
                float rh0 = sig_(accR[mt][nt][half * 2]) * hv.x;
                float rh1 = sig_(accR[mt][nt][half * 2 + 1]) * hv.y;
                const int rbm = (rbase >> 4);
                const int regidx = half + 2 * (nt & 1);
                rhp32[((rbm * 64 + kb) * 32 + lane) * 4 + regidx] = h2u(rh0, rh1);
            }
        }
    }
}

// ---------------------------------------------------------------------------
// Kernel 2 (R9 verbatim): block 128x64, 8 warps (4m x 2n), warp 32x32, BK=64,
// 3-stage ring. smem/stage (uint4): A 1024 | B 512. 72KB, 3 CTAs/SM.
// ---------------------------------------------------------------------------
__global__ void __launch_bounds__(256, 3) gemm_ht(const float* __restrict__ h,
                                                  float* __restrict__ out) {
    extern __shared__ uint4 sm4[];
    const int tid = threadIdx.x, wid = tid >> 5, lane = tid & 31;
    const int g = lane >> 2, tq = lane & 3;
    const int mrow = wid & 3, ncol = wid >> 2;   // 4 x 2 warps, warp 32x32
    const int bm = blockIdx.x * 128, bn = blockIdx.y * 64;
    const int rb0 = bm >> 4, nb0 = bn >> 3;

    auto stage = [&](int t) {
        const int seg = t >> 4, kb0 = (t & 15) * 4;
        const uint4* Ag = seg ? g_xp : g_rhp;
        const uint4* Bg = reinterpret_cast<const uint4*>(g_Wh[seg ? 5 : 4]);
        uint4* dst = &sm4[(t % 3) * 1536];
        #pragma unroll
        for (int i = 0; i < 4; i++) {
            int c = tid + i * 256, rbl = c >> 7, rem = c & 127;
            cp_async16(&dst[c], &Ag[((rb0 + rbl) * 64 + kb0) * 32 + rem]);
        }
        #pragma unroll
        for (int i = 0; i < 2; i++) {
            int c = tid + i * 256, nbl = c >> 6, rem = c & 63;
            cp_async16(&dst[1024 + c], &Bg[((nb0 + nbl) * 64 + kb0) * 16 + rem]);
        }
        cp_commit();
    };

    float acc[2][4][4] = {};
    stage(0);
    stage(1);

    for (int t = 0; t < 32; t++) {
        if (t + 2 < 32) cp_wait1(); else cp_wait0();
        __syncthreads();
        if (t + 2 < 32) stage(t + 2);
        const uint4* A_ = &sm4[(t % 3) * 1536];
        const uint2* B_ = reinterpret_cast<const uint2*>(&A_[1024]);
        #pragma unroll
        for (int kk = 0; kk < 4; kk++) {
            uint4 a0 = A_[((mrow * 2 + 0) * 4 + kk) * 32 + lane];
            uint4 a1 = A_[((mrow * 2 + 1) * 4 + kk) * 32 + lane];
            #pragma unroll
            for (int n = 0; n < 4; n++) {
                uint2 b = B_[((ncol * 4 + n) * 4 + kk) * 32 + lane];
                mma16(acc[0][n], a0, b);
                mma16(acc[1][n], a1, b);
            }
        }
    }

    #pragma unroll
    for (int r = 0; r < 2; r++) {
        const int rowbase = bm + mrow * 32 + r * 16;
        #pragma unroll
        for (int n = 0; n < 4; n++) {
            const int col = bn + ncol * 32 + n * 8 + tq * 2;
            #pragma unroll
            for (int half = 0; half < 2; half++) {
                const int idx = (rowbase + half * 8 + g) * HH + col;
                float2 hv = *reinterpret_cast<const float2*>(&h[idx]);
                float2 zv = *reinterpret_cast<const float2*>(&g_Z[idx]);
                float2 ov;
                ov.x = zv.x * hv.x + (1.0f - zv.x) * ftanh_(acc[r][n][half * 2]);
                ov.y = zv.y * hv.y + (1.0f - zv.y) * ftanh_(acc[r][n][half * 2 + 1]);
                *reinterpret_cast<float2*>(&out[idx]) = ov;
            }
        }
    }
}

// ---------------------------------------------------------------------------
extern "C" void kernel_launch(void* const* d_in, const int* in_sizes, int n_in,
                              void* d_out, int out_size) {
    const float* x   = (const float*)d_in[0];
    const float* h   = (const float*)d_in[1];
    const float* Wwz = (const float*)d_in[2];
    const float* Wuz = (const float*)d_in[3];
    const float* Wwr = (const float*)d_in[4];
    const float* Wur = (const float*)d_in[5];
    const float* Wu  = (const float*)d_in[6];
    const float* Ww  = (const float*)d_in[7];
    float* out = (float*)d_out;

    const int s1 = 6144 * 16;   // 96 KB
    const int s2 = 4608 * 16;   // 72 KB
    cudaFuncSetAttribute(gemm_zr, cudaFuncAttributeMaxDynamicSharedMemorySize, s1);
    cudaFuncSetAttribute(gemm_ht, cudaFuncAttributeMaxDynamicSharedMemorySize, s2);

    perm_all<<<14336, 256>>>(x, h, Wwz, Wuz, Wwr, Wur, Wu, Ww);
    gemm_zr<<<dim3(64, 16), 256, s1>>>(h);
    gemm_ht<<<dim3(64, 16), 256, s2>>>(h, out);
}